// round 9
// baseline (speedup 1.0000x reference)
#include <cuda_runtime.h>
#include <cstdint>

// TaylorMap: out = x + poly3(x) @ W     (scalar FFMA2 path, R5 lineage)
//   x : [262144, 16] f32,  W : [969, 16] f32,  out : [262144, 16] f32
//
// Feature ordering (matches reference _poly):
//   row 0          : 1
//   rows 1..16     : x_i          (identity residual folded into these rows)
//   rows 17..152   : x_a * x_b   (a>=b)     -> 17 + a(a+1)/2 + b
//   rows 153..968  : x_i*x_a*x_b (i>=a>=b)  -> 153 + C(ii+2,3) + a(a+1)/2 + b
//
// R9 = R5 (CTA column split, 8 cols/CTA, 31KB smem, 3 CTAs/SM, 6 warps/SMSP,
// 2-row x 8-col thread tile, per-half tickets) + explicit depth-1 software
// pipeline on the W shared loads: each APPLY prefetches the NEXT feature
// row's two 16B W halves into rotating double buffers while running the
// current row's FFMA2s. Next-row indices are compile-time constants at every
// site of the fully unrolled traversal.

#define NF 16
#define NPOLY 969
#define BLOCK 256
#define GRID 444                 // 3 CTAs/SM x 148 SMs; 222 CTAs per col-half
#define NBATCH 262144
#define CHUNK_ROWS 64            // per warp-ticket (32 threads x 2 rows)
#define NCHUNK (NBATCH / CHUNK_ROWS)   // 4096 row chunks (per column half)

typedef unsigned long long u64;

__device__ unsigned int g_tickets[2];
__global__ void reset_ticket_kernel() { g_tickets[0] = 0u; g_tickets[1] = 0u; }

__device__ __forceinline__ u64 pk2(float lo, float hi) {
    u64 r; asm("mov.b64 %0, {%1, %2};" : "=l"(r) : "f"(lo), "f"(hi)); return r;
}
__device__ __forceinline__ void upk2(u64 v, float& lo, float& hi) {
    asm("mov.b64 {%0, %1}, %2;" : "=f"(lo), "=f"(hi) : "l"(v));
}
__device__ __forceinline__ float lo2(u64 v) { float a, b; upk2(v, a, b); return a; }
__device__ __forceinline__ float hi2(u64 v) { float a, b; upk2(v, a, b); return b; }
__device__ __forceinline__ u64 dup_lo(u64 v) { float a = lo2(v); return pk2(a, a); }
__device__ __forceinline__ u64 dup_hi(u64 v) { float a = hi2(v); return pk2(a, a); }

__device__ __forceinline__ u64 f2fma(u64 a, u64 b, u64 c) {
    u64 d; asm("fma.rn.f32x2 %0, %1, %2, %3;" : "=l"(d) : "l"(a), "l"(b), "l"(c)); return d;
}
__device__ __forceinline__ u64 f2mul(u64 a, u64 b) {
    u64 d; asm("mul.rn.f32x2 %0, %1, %2;" : "=l"(d) : "l"(a), "l"(b)); return d;
}

// Per-CTA smem: 8 columns of W for all 969 rows, row stride 32B.
#define SMEM_BYTES (NPOLY * 8 * 4)    // 31,008 B

// feature-row index helpers (fold to constants after unroll)
#define ROW2(a, b)    (17 + ((a) * ((a) + 1)) / 2 + (b))
#define ROW3(i, a, b) (153 + ((i) * ((i) + 1) * ((i) + 2)) / 6 \
                       + ((a) * ((a) + 1)) / 2 + (b))

__global__ void __launch_bounds__(BLOCK, 3)
taylor_kernel(const float* __restrict__ x, const float* __restrict__ W,
              float* __restrict__ out)
{
    extern __shared__ unsigned char smem_raw[];
    float* sW = reinterpret_cast<float*>(smem_raw);   // [969][8]

    const int tid  = threadIdx.x;
    const int half = (int)blockIdx.x & 1;             // cols [8*half, 8*half+8)

    // Cooperative load of this CTA's 8 W columns; fold identity residual:
    // out = x + poly@W  ==  poly@W'  with  W'[1+i][i] += 1.
    #pragma unroll 1
    for (int e = tid; e < NPOLY * 8; e += BLOCK) {
        int row = e >> 3, c = e & 7;
        int col = 8 * half + c;
        float w = W[row * NF + col];
        if (row - 1 == col) w += 1.0f;
        sW[e] = w;
    }
    __syncthreads();

    const int lane = tid & 31;
    const char* wbase = reinterpret_cast<const char*>(sW);
    const long long colbase = 8 * half;

    for (;;) {
        // ---- warp grabs a 64-row chunk ticket (per column half) ----
        unsigned int t;
        if (lane == 0) t = atomicAdd(&g_tickets[half], 1u);
        t = __shfl_sync(0xffffffffu, t, 0);
        if (t >= NCHUNK) break;

        const long long r0 = (long long)t * CHUNK_ROWS + lane * 2;  // rows r0, r0+1

        // ---- load 2 rows of x, pack as row-pairs ----
        const float4* xv = reinterpret_cast<const float4*>(x + r0 * NF);
        u64 xx[NF];
        #pragma unroll
        for (int q = 0; q < 4; q++) {
            float4 a = xv[q];        // row 0
            float4 b = xv[4 + q];    // row 1
            xx[q * 4 + 0] = pk2(a.x, b.x);
            xx[q * 4 + 1] = pk2(a.y, b.y);
            xx[q * 4 + 2] = pk2(a.z, b.z);
            xx[q * 4 + 3] = pk2(a.w, b.w);
        }

        // ---- acc[r*4 + c] = output cols (colbase+2c, +2c+1) of row r ----
        u64 acc[8];
        {   // degree-0 init: acc = W'[0][cols] (identity lives in deg-1 rows)
            const ulonglong2* wp = reinterpret_cast<const ulonglong2*>(wbase);
            ulonglong2 w0 = wp[0], w1 = wp[1];
            acc[0] = w0.x; acc[1] = w0.y; acc[2] = w1.x; acc[3] = w1.y;
            acc[4] = w0.x; acc[5] = w0.y; acc[6] = w1.x; acc[7] = w1.y;
        }

        // ---- software-pipelined traversal ----
        // Double-buffered W row (two 16B halves). Entry e consumes buffer
        // [e&1] (loaded at entry e-1) and prefetches NROW into [1 - (e&1)].
        ulonglong2 w0b[2], w1b[2];
        w0b[0] = *reinterpret_cast<const ulonglong2*>(wbase + 1 * 32);
        w1b[0] = *reinterpret_cast<const ulonglong2*>(wbase + 1 * 32 + 16);
        u64 pc = xx[0];   // monomial cache for deg-3 runs (init: dummy)
        int ecnt = 0;     // entry counter; folds to constants after unroll

        // KIND: 1 = x_i, 2 = x_a*x_b (caches pc), 3 = x_i*pc
        #define PAPPLY(KIND, I0, I1, NROW) do {                                  \
            const int _p = ecnt & 1;                                             \
            u64 m;                                                               \
            if ((KIND) == 1)      m = xx[(I0)];                                  \
            else if ((KIND) == 2) { pc = f2mul(xx[(I0)], xx[(I1)]); m = pc; }    \
            else                  m = f2mul(xx[(I0)], pc);                       \
            u64 d0 = dup_lo(m), d1 = dup_hi(m);                                  \
            w0b[_p ^ 1] = *reinterpret_cast<const ulonglong2*>(                  \
                              wbase + (NROW) * 32);                              \
            acc[0] = f2fma(d0, w0b[_p].x, acc[0]);                               \
            acc[1] = f2fma(d0, w0b[_p].y, acc[1]);                               \
            acc[4] = f2fma(d1, w0b[_p].x, acc[4]);                               \
            acc[5] = f2fma(d1, w0b[_p].y, acc[5]);                               \
            w1b[_p ^ 1] = *reinterpret_cast<const ulonglong2*>(                  \
                              wbase + (NROW) * 32 + 16);                         \
            acc[2] = f2fma(d0, w1b[_p].x, acc[2]);                               \
            acc[3] = f2fma(d0, w1b[_p].y, acc[3]);                               \
            acc[6] = f2fma(d1, w1b[_p].x, acc[6]);                               \
            acc[7] = f2fma(d1, w1b[_p].y, acc[7]);                               \
            ecnt++;                                                              \
        } while (0)

        // degree 1 (identity already folded into W'); next after i=15 is ROW2(0,0)
        #pragma unroll
        for (int i = 0; i < NF; i++)
            PAPPLY(1, i, 0, (i < 15) ? (2 + i) : ROW2(0, 0));

        // degree 2 & 3 fused: deg2(a,b) then deg3(ii=a..15,a,b)
        #pragma unroll
        for (int ia = 0; ia < NF; ia++) {
            #pragma unroll
            for (int ib = 0; ib <= ia; ib++) {
                // next row after deg2(ia,ib) is deg3(ia,ia,ib)
                PAPPLY(2, ia, ib, ROW3(ia, ia, ib));
                #pragma unroll
                for (int ii = ia; ii < NF; ii++) {
                    const int nrow =
                        (ii < 15) ? ROW3(ii + 1, ia, ib)
                        : (ib < ia) ? ROW2(ia, ib + 1)
                        : (ia < 15) ? ROW2(ia + 1, 0)
                        : 1;                       // last entry: harmless reload
                    PAPPLY(3, ii, 0, nrow);
                }
            }
        }
        #undef PAPPLY

        // ---- store 2 rows x 8 cols ----
        {
            ulonglong2 s0; s0.x = acc[0]; s0.y = acc[1];
            ulonglong2 s1; s1.x = acc[2]; s1.y = acc[3];
            ulonglong2* op0 =
                reinterpret_cast<ulonglong2*>(out + r0 * NF + colbase);
            op0[0] = s0; op0[1] = s1;
            ulonglong2 s2; s2.x = acc[4]; s2.y = acc[5];
            ulonglong2 s3; s3.x = acc[6]; s3.y = acc[7];
            ulonglong2* op1 =
                reinterpret_cast<ulonglong2*>(out + (r0 + 1) * NF + colbase);
            op1[0] = s2; op1[1] = s3;
        }
    }
}

extern "C" void kernel_launch(void* const* d_in, const int* in_sizes, int n_in,
                              void* d_out, int out_size)
{
    const float* x = (const float*)d_in[0];   // [262144, 16]
    const float* W = (const float*)d_in[1];   // [969, 16]
    float* out = (float*)d_out;

    cudaFuncSetAttribute(taylor_kernel,
                         cudaFuncAttributeMaxDynamicSharedMemorySize,
                         SMEM_BYTES);

    reset_ticket_kernel<<<1, 1>>>();
    taylor_kernel<<<GRID, BLOCK, SMEM_BYTES>>>(x, W, out);
}

// round 10
// speedup vs baseline: 1.5673x; 1.5673x over previous
#include <cuda_runtime.h>
#include <cstdint>

// TaylorMap: out = x + poly3(x) @ W     (scalar FFMA2 path)
//   x : [262144, 16] f32,  W : [969, 16] f32,  out : [262144, 16] f32
//
// Feature ordering (matches reference _poly):
//   row 0          : 1
//   rows 1..16     : x_i          (identity residual folded into these rows)
//   rows 17..152   : x_a * x_b   (a>=b)     -> 17 + a(a+1)/2 + b
//   rows 153..968  : x_i*x_a*x_b (i>=a>=b)  -> 153 + C(ii+2,3) + a(a+1)/2 + b
//
// R10 = R5 (CTA column split: 8 cols/CTA, 31KB smem, 3 CTAs/SM, 6 warps/SMSP,
// 2-row x 8-col thread tile, per-half atomic tickets) + depth-1 software
// pipeline on the W shared loads implemented with NAMED variables only
// (R9's register-array double buffer was demoted to local memory -> 991us).
// Rotation copies (cw = nw) are SSA-renamed away after full unroll.

#define NF 16
#define NPOLY 969
#define BLOCK 256
#define GRID 444                 // 3 CTAs/SM x 148 SMs; 222 CTAs per col-half
#define NBATCH 262144
#define CHUNK_ROWS 64            // per warp-ticket (32 threads x 2 rows)
#define NCHUNK (NBATCH / CHUNK_ROWS)   // 4096 row chunks (per column half)

typedef unsigned long long u64;

__device__ unsigned int g_tickets[2];
__global__ void reset_ticket_kernel() { g_tickets[0] = 0u; g_tickets[1] = 0u; }

__device__ __forceinline__ u64 pk2(float lo, float hi) {
    u64 r; asm("mov.b64 %0, {%1, %2};" : "=l"(r) : "f"(lo), "f"(hi)); return r;
}
__device__ __forceinline__ void upk2(u64 v, float& lo, float& hi) {
    asm("mov.b64 {%0, %1}, %2;" : "=f"(lo), "=f"(hi) : "l"(v));
}
__device__ __forceinline__ float lo2(u64 v) { float a, b; upk2(v, a, b); return a; }
__device__ __forceinline__ float hi2(u64 v) { float a, b; upk2(v, a, b); return b; }
__device__ __forceinline__ u64 dup_lo(u64 v) { float a = lo2(v); return pk2(a, a); }
__device__ __forceinline__ u64 dup_hi(u64 v) { float a = hi2(v); return pk2(a, a); }

__device__ __forceinline__ u64 f2fma(u64 a, u64 b, u64 c) {
    u64 d; asm("fma.rn.f32x2 %0, %1, %2, %3;" : "=l"(d) : "l"(a), "l"(b), "l"(c)); return d;
}
__device__ __forceinline__ u64 f2mul(u64 a, u64 b) {
    u64 d; asm("mul.rn.f32x2 %0, %1, %2;" : "=l"(d) : "l"(a), "l"(b)); return d;
}

// Per-CTA smem: 8 columns of W for all 969 rows, row stride 32B.
#define SMEM_BYTES (NPOLY * 8 * 4)    // 31,008 B

// feature-row index helpers (fold to constants after unroll)
#define ROW2(a, b)    (17 + ((a) * ((a) + 1)) / 2 + (b))
#define ROW3(i, a, b) (153 + ((i) * ((i) + 1) * ((i) + 2)) / 6 \
                       + ((a) * ((a) + 1)) / 2 + (b))

__global__ void __launch_bounds__(BLOCK, 3)
taylor_kernel(const float* __restrict__ x, const float* __restrict__ W,
              float* __restrict__ out)
{
    extern __shared__ unsigned char smem_raw[];
    float* sW = reinterpret_cast<float*>(smem_raw);   // [969][8]

    const int tid  = threadIdx.x;
    const int half = (int)blockIdx.x & 1;             // cols [8*half, 8*half+8)

    // Cooperative load of this CTA's 8 W columns; fold identity residual:
    // out = x + poly@W  ==  poly@W'  with  W'[1+i][i] += 1.
    #pragma unroll 1
    for (int e = tid; e < NPOLY * 8; e += BLOCK) {
        int row = e >> 3, c = e & 7;
        int col = 8 * half + c;
        float w = W[row * NF + col];
        if (row - 1 == col) w += 1.0f;
        sW[e] = w;
    }
    __syncthreads();

    const int lane = tid & 31;
    const char* wbase = reinterpret_cast<const char*>(sW);
    const long long colbase = 8 * half;

    for (;;) {
        // ---- warp grabs a 64-row chunk ticket (per column half) ----
        unsigned int t;
        if (lane == 0) t = atomicAdd(&g_tickets[half], 1u);
        t = __shfl_sync(0xffffffffu, t, 0);
        if (t >= NCHUNK) break;

        const long long r0 = (long long)t * CHUNK_ROWS + lane * 2;  // rows r0, r0+1

        // ---- load 2 rows of x, pack as row-pairs ----
        const float4* xv = reinterpret_cast<const float4*>(x + r0 * NF);
        u64 xx[NF];
        #pragma unroll
        for (int q = 0; q < 4; q++) {
            float4 a = xv[q];        // row 0
            float4 b = xv[4 + q];    // row 1
            xx[q * 4 + 0] = pk2(a.x, b.x);
            xx[q * 4 + 1] = pk2(a.y, b.y);
            xx[q * 4 + 2] = pk2(a.z, b.z);
            xx[q * 4 + 3] = pk2(a.w, b.w);
        }

        // ---- acc[r*4 + c] = output cols (colbase+2c, +2c+1) of row r ----
        u64 acc[8];
        {   // degree-0 init: acc = W'[0][cols] (identity lives in deg-1 rows)
            const ulonglong2* wp = reinterpret_cast<const ulonglong2*>(wbase);
            ulonglong2 w0 = wp[0], w1 = wp[1];
            acc[0] = w0.x; acc[1] = w0.y; acc[2] = w1.x; acc[3] = w1.y;
            acc[4] = w0.x; acc[5] = w0.y; acc[6] = w1.x; acc[7] = w1.y;
        }

        // ---- software-pipelined traversal: NAMED double buffer ----
        ulonglong2 cw0 = *reinterpret_cast<const ulonglong2*>(wbase + 1 * 32);
        ulonglong2 cw1 = *reinterpret_cast<const ulonglong2*>(wbase + 1 * 32 + 16);
        u64 pc = xx[0];   // monomial cache for deg-3 runs (dummy init)

        // KIND: 1 = x_i, 2 = x_a*x_b (caches pc), 3 = x_i*pc.
        // Consumes cw0/cw1 (current row), prefetches NROW into nw0/nw1,
        // rotates by plain assignment (copy-propagated in SSA after unroll).
        #define PAPPLY(KIND, I0, I1, NROW) do {                                  \
            u64 m;                                                               \
            if ((KIND) == 1)      m = xx[(I0)];                                  \
            else if ((KIND) == 2) { pc = f2mul(xx[(I0)], xx[(I1)]); m = pc; }    \
            else                  m = f2mul(xx[(I0)], pc);                       \
            u64 d0 = dup_lo(m), d1 = dup_hi(m);                                  \
            ulonglong2 nw0 = *reinterpret_cast<const ulonglong2*>(               \
                                 wbase + (NROW) * 32);                           \
            ulonglong2 nw1 = *reinterpret_cast<const ulonglong2*>(               \
                                 wbase + (NROW) * 32 + 16);                      \
            acc[0] = f2fma(d0, cw0.x, acc[0]);                                   \
            acc[1] = f2fma(d0, cw0.y, acc[1]);                                   \
            acc[4] = f2fma(d1, cw0.x, acc[4]);                                   \
            acc[5] = f2fma(d1, cw0.y, acc[5]);                                   \
            acc[2] = f2fma(d0, cw1.x, acc[2]);                                   \
            acc[3] = f2fma(d0, cw1.y, acc[3]);                                   \
            acc[6] = f2fma(d1, cw1.x, acc[6]);                                   \
            acc[7] = f2fma(d1, cw1.y, acc[7]);                                   \
            cw0 = nw0; cw1 = nw1;                                                \
        } while (0)

        // degree 1 (identity folded); successor of i=15 is ROW2(0,0)
        #pragma unroll
        for (int i = 0; i < NF; i++)
            PAPPLY(1, i, 0, (i < 15) ? (2 + i) : ROW2(0, 0));

        // degree 2 & 3 fused: deg2(ia,ib) then deg3(ii=ia..15, ia, ib)
        #pragma unroll
        for (int ia = 0; ia < NF; ia++) {
            #pragma unroll
            for (int ib = 0; ib <= ia; ib++) {
                PAPPLY(2, ia, ib, ROW3(ia, ia, ib));
                #pragma unroll
                for (int ii = ia; ii < NF; ii++) {
                    const int nrow =
                        (ii < 15) ? ROW3(ii + 1, ia, ib)
                        : (ib < ia) ? ROW2(ia, ib + 1)
                        : (ia < 15) ? ROW2(ia + 1, 0)
                        : 1;                       // final entry: harmless
                    PAPPLY(3, ii, 0, nrow);
                }
            }
        }
        #undef PAPPLY

        // ---- store 2 rows x 8 cols ----
        {
            ulonglong2 s0; s0.x = acc[0]; s0.y = acc[1];
            ulonglong2 s1; s1.x = acc[2]; s1.y = acc[3];
            ulonglong2* op0 =
                reinterpret_cast<ulonglong2*>(out + r0 * NF + colbase);
            op0[0] = s0; op0[1] = s1;
            ulonglong2 s2; s2.x = acc[4]; s2.y = acc[5];
            ulonglong2 s3; s3.x = acc[6]; s3.y = acc[7];
            ulonglong2* op1 =
                reinterpret_cast<ulonglong2*>(out + (r0 + 1) * NF + colbase);
            op1[0] = s2; op1[1] = s3;
        }
    }
}

extern "C" void kernel_launch(void* const* d_in, const int* in_sizes, int n_in,
                              void* d_out, int out_size)
{
    const float* x = (const float*)d_in[0];   // [262144, 16]
    const float* W = (const float*)d_in[1];   // [969, 16]
    float* out = (float*)d_out;

    cudaFuncSetAttribute(taylor_kernel,
                         cudaFuncAttributeMaxDynamicSharedMemorySize,
                         SMEM_BYTES);

    reset_ticket_kernel<<<1, 1>>>();
    taylor_kernel<<<GRID, BLOCK, SMEM_BYTES>>>(x, W, out);
}

// round 13
// speedup vs baseline: 17.0611x; 10.8860x over previous
#include <cuda_runtime.h>
#include <cstdint>

// TaylorMap via classic mma.sync m16n8k16 f16/f32 (sm_103: no tcgen05).
//   out = x + P(x) @ W,  P:[B,969->992] monomials (reference order) in f16.
// R13 = R12 with the traversal fixed back to R8's ASCENDING-k order (R12's
// pair-based order scrambled the f16 pend-pairing and cstep interleave ->
// rel_err 0.5). Generation forced to full unroll via template<int KK> +
// if constexpr; all data paths byte-identical to R8 (rel_err 1.1e-4).

typedef unsigned int u32;
typedef unsigned long long u64;

#define NF 16
#define KTOT 992
#define NSTEP 62
#define BLOCK 256
#define GRID 296                    // 2 CTAs/SM
#define NBATCH 262144
#define NTILES (NBATCH / 32)        // 8192 tiles of 32 rows
#define BFRAG_BYTES (NSTEP * 32 * 16)     // 31744
#define PSM_OFF BFRAG_BYTES
#define PSM_PER_WARP 8192           // two 4KB chunk buffers
#define SMEM_TOTAL (BFRAG_BYTES + 8 * PSM_PER_WARP)   // 97280

#define ROW2(a, b)    (17 + ((a) * ((a) + 1)) / 2 + (b))
#define ROW3(i, a, b) (153 + ((i) * ((i) + 1) * ((i) + 2)) / 6 \
                       + ((a) * ((a) + 1)) / 2 + (b))

__device__ unsigned int g_ticket;
__global__ void reset_ticket_kernel() { g_ticket = 0u; }

__device__ __forceinline__ u32 smem_u32(const void* p) {
    u32 a;
    asm("{ .reg .u64 t; cvta.to.shared.u64 t, %1; cvt.u32.u64 %0, t; }"
        : "=r"(a) : "l"(p));
    return a;
}
__device__ __forceinline__ u32 packf16(float hi, float lo) {
    u32 r; asm("cvt.rn.f16x2.f32 %0, %1, %2;" : "=r"(r) : "f"(hi), "f"(lo));
    return r;
}
__device__ __forceinline__ u32 lds32(u32 addr) {
    u32 v; asm volatile("ld.shared.b32 %0, [%1];" : "=r"(v) : "r"(addr));
    return v;
}
__device__ __forceinline__ void sts32(u32 addr, u32 v) {
    asm volatile("st.shared.b32 [%0], %1;" :: "r"(addr), "r"(v));
}

// ---- tiny integer-sequence machinery (no std headers) ----
template <int... Is> struct ISeq {};
template <int N, int... Is> struct MkSeq : MkSeq<N - 1, N - 1, Is...> {};
template <int... Is> struct MkSeq<0, Is...> { using T = ISeq<Is...>; };

// flat pair index p -> (a, b) with a >= b, p = a(a+1)/2 + b
__host__ __device__ constexpr int pair_a(int p) {
    int a = 0;
    while ((a + 1) * (a + 2) / 2 <= p) a++;
    return a;
}

// ---- shared context parameter pack ----
#define CTX_DECL float (&xs)[16], float& pend,                                 \
    const u32 rst0, const u32 rst1, const u32 rst2, const u32 rst3,            \
    const u32 ao0, const u32 ao1, const u32 ao2, const u32 ao3, const u32 rb,  \
    float& d00, float& d01, float& d02, float& d03,                            \
    float& d10, float& d11, float& d12, float& d13,                            \
    float& d20, float& d21, float& d22, float& d23,                            \
    float& d30, float& d31, float& d32, float& d33
#define CTX_ARGS xs, pend, rst0, rst1, rst2, rst3, ao0, ao1, ao2, ao3, rb,     \
    d00, d01, d02, d03, d10, d11, d12, d13, d20, d21, d22, d23, d30, d31, d32, d33

// One consume k-step (chunk CH, step S) — all offsets compile-time.
template <int CH, int S>
__device__ __forceinline__ void cstep(CTX_DECL) {
    u32 b0, b1, b2, b3;
    asm volatile("ld.shared.v4.b32 {%0,%1,%2,%3}, [%4];"
        : "=r"(b0), "=r"(b1), "=r"(b2), "=r"(b3)
        : "r"(rb + (u32)((4 * CH + S) * 512)));
    constexpr u32 IMM = (u32)(((CH & 1) * 4096) + S * 1024);
    u32 a0 = lds32(ao0 + IMM);
    u32 a1 = lds32(ao1 + IMM);
    u32 a2 = lds32(ao0 + IMM + 512);
    u32 a3 = lds32(ao1 + IMM + 512);
    asm volatile("mma.sync.aligned.m16n8k16.row.col.f32.f16.f16.f32 "
        "{%0,%1,%2,%3}, {%4,%5,%6,%7}, {%8,%9}, {%0,%1,%2,%3};"
        : "+f"(d00), "+f"(d01), "+f"(d02), "+f"(d03)
        : "r"(a0), "r"(a1), "r"(a2), "r"(a3), "r"(b0), "r"(b1));
    asm volatile("mma.sync.aligned.m16n8k16.row.col.f32.f16.f16.f32 "
        "{%0,%1,%2,%3}, {%4,%5,%6,%7}, {%8,%9}, {%0,%1,%2,%3};"
        : "+f"(d10), "+f"(d11), "+f"(d12), "+f"(d13)
        : "r"(a0), "r"(a1), "r"(a2), "r"(a3), "r"(b2), "r"(b3));
    u32 a4 = lds32(ao2 + IMM);
    u32 a5 = lds32(ao3 + IMM);
    u32 a6 = lds32(ao2 + IMM + 512);
    u32 a7 = lds32(ao3 + IMM + 512);
    asm volatile("mma.sync.aligned.m16n8k16.row.col.f32.f16.f16.f32 "
        "{%0,%1,%2,%3}, {%4,%5,%6,%7}, {%8,%9}, {%0,%1,%2,%3};"
        : "+f"(d20), "+f"(d21), "+f"(d22), "+f"(d23)
        : "r"(a4), "r"(a5), "r"(a6), "r"(a7), "r"(b0), "r"(b1));
    asm volatile("mma.sync.aligned.m16n8k16.row.col.f32.f16.f16.f32 "
        "{%0,%1,%2,%3}, {%4,%5,%6,%7}, {%8,%9}, {%0,%1,%2,%3};"
        : "+f"(d30), "+f"(d31), "+f"(d32), "+f"(d33)
        : "r"(a4), "r"(a5), "r"(a6), "r"(a7), "r"(b2), "r"(b3));
}

// Emit monomial KK (STRICTLY ASCENDING KK across all call sites):
// pack f16 pairs, store swizzled, interleave one consume step of the
// previous chunk every 16 k, syncwarp at each 64-k chunk end.
template <int KK>
__device__ __forceinline__ void emitk(float v, CTX_DECL) {
    if constexpr ((KK & 1) == 0) {
        pend = v;
    } else {
        u32 h = packf16(v, pend);
        constexpr int kp = KK >> 1;
        constexpr u32 off = (u32)((((kp >> 5) & 1) * 4096) + (kp & 31) * 128);
        constexpr int sel = kp & 3;
        u32 base = (sel == 0) ? rst0 : (sel == 1) ? rst1
                 : (sel == 2) ? rst2 : rst3;
        sts32(base + off, h);
        if constexpr (KK >= 79 && (KK & 15) == 15) {
            cstep<(KK >> 6) - 1, (KK >> 4) & 3>(CTX_ARGS);
        }
        if constexpr ((KK & 63) == 63) { __syncwarp(); }
    }
}

// ---- ascending-k traversal (mirrors R8 exactly) ----

// degree 1: k = 1 + i
template <int... Is>
__device__ __forceinline__ void do_deg1(ISeq<Is...>, CTX_DECL) {
    (emitk<1 + Is>(xs[Is], CTX_ARGS), ...);
}

// degree 2: pair P ascending -> k = 17 + P (contiguous)
template <int P>
__device__ __forceinline__ void do_p2(CTX_DECL) {
    constexpr int A = pair_a(P);
    constexpr int B = P - A * (A + 1) / 2;
    emitk<17 + P>(xs[A] * xs[B], CTX_ARGS);
}
template <int... Ps>
__device__ __forceinline__ void do_deg2(ISeq<Ps...>, CTX_DECL) {
    (do_p2<Ps>(CTX_ARGS), ...);
}

// degree 3: II outer; for each (II, A) run B = 0..A with tp = xs[II]*xs[A].
// k = ROW3(II, A, B): contiguous within II block, blocks abut.
template <int II, int A, int... Bs>
__device__ __forceinline__ void emit3run(float tp, ISeq<Bs...>, CTX_DECL) {
    (emitk<ROW3(II, A, Bs)>(tp * xs[Bs], CTX_ARGS), ...);
}
template <int II, int... As>
__device__ __forceinline__ void do_ii(ISeq<As...>, CTX_DECL) {
    (emit3run<II, As>(xs[II] * xs[As], typename MkSeq<As + 1>::T{}, CTX_ARGS), ...);
}
template <int... IIs>
__device__ __forceinline__ void do_deg3(ISeq<IIs...>, CTX_DECL) {
    (do_ii<IIs>(typename MkSeq<IIs + 1>::T{}, CTX_ARGS), ...);
}

// zero pad: k = 969..991
template <int... Js>
__device__ __forceinline__ void do_pad(ISeq<Js...>, CTX_DECL) {
    (emitk<969 + Js>(0.0f, CTX_ARGS), ...);
}

__global__ void __launch_bounds__(BLOCK, 2)
taylor_mma(const float* __restrict__ x, const float* __restrict__ W,
           float* __restrict__ out)
{
    extern __shared__ unsigned char smem[];
    const u32 sbase = smem_u32(smem);
    const int tid = threadIdx.x;
    const int warp = tid >> 5;
    const int lane = tid & 31;
    const int g = lane >> 2;          // fragment row group 0..7
    const int t = lane & 3;           // thread-in-group 0..3

    // ---- build B fragments once (validated in R7/R8) ----
#pragma unroll 1
    for (int e = tid; e < NSTEP * 32; e += BLOCK) {
        int s = e >> 5, l = e & 31;
        int lg = l >> 2, lt = l & 3;
        int k1 = 16 * s + 2 * lt;
#define WGET(K, C) (((K) < 969) ? W[(K) * NF + (C)] : 0.0f)
        uint4 v;
        v.x = packf16(WGET(k1 + 1, lg),     WGET(k1, lg));
        v.y = packf16(WGET(k1 + 9, lg),     WGET(k1 + 8, lg));
        v.z = packf16(WGET(k1 + 1, lg + 8), WGET(k1, lg + 8));
        v.w = packf16(WGET(k1 + 9, lg + 8), WGET(k1 + 8, lg + 8));
#undef WGET
        *reinterpret_cast<uint4*>(smem + e * 16) = v;
    }
    __syncthreads();

    // ---- per-lane smem bases ----
    const u32 psmw = sbase + PSM_OFF + warp * PSM_PER_WARP;
    const u32 cp0 = ((lane & 7) << 2) + (lane >> 3);
    const u32 rst0 = psmw + ((cp0 ^ 0) << 2);
    const u32 rst1 = psmw + ((cp0 ^ 1) << 2);
    const u32 rst2 = psmw + ((cp0 ^ 2) << 2);
    const u32 rst3 = psmw + ((cp0 ^ 3) << 2);
    const u32 ao0 = psmw + (u32)(t * 128) + ((((g << 2) + 0) ^ t) << 2);
    const u32 ao1 = psmw + (u32)(t * 128) + ((((g << 2) + 1) ^ t) << 2);
    const u32 ao2 = psmw + (u32)(t * 128) + ((((g << 2) + 2) ^ t) << 2);
    const u32 ao3 = psmw + (u32)(t * 128) + ((((g << 2) + 3) ^ t) << 2);
    const u32 rb = sbase + lane * 16;

    for (;;) {
        u32 tk;
        if (lane == 0) tk = atomicAdd(&g_ticket, 1u);
        tk = __shfl_sync(0xffffffffu, tk, 0);
        if (tk >= NTILES) break;

        const long long base = (long long)tk * 32;

        const float4* xv = reinterpret_cast<const float4*>(x + (base + lane) * NF);
        float4 v0 = xv[0], v1 = xv[1], v2 = xv[2], v3 = xv[3];
        float xs[NF] = { v0.x, v0.y, v0.z, v0.w,  v1.x, v1.y, v1.z, v1.w,
                         v2.x, v2.y, v2.z, v2.w,  v3.x, v3.y, v3.z, v3.w };

        float d00 = 0, d01 = 0, d02 = 0, d03 = 0;   // su0,nt0
        float d10 = 0, d11 = 0, d12 = 0, d13 = 0;   // su0,nt1
        float d20 = 0, d21 = 0, d22 = 0, d23 = 0;   // su1,nt0
        float d30 = 0, d31 = 0, d32 = 0, d33 = 0;   // su1,nt1
        float pend = 0.0f;

        // ---- fully-expanded generation, ascending k = 0..991 ----
        emitk<0>(1.0f, CTX_ARGS);
        do_deg1(typename MkSeq<16>::T{}, CTX_ARGS);
        do_deg2(typename MkSeq<136>::T{}, CTX_ARGS);
        do_deg3(typename MkSeq<16>::T{}, CTX_ARGS);
        do_pad(typename MkSeq<KTOT - 969>::T{}, CTX_ARGS);

        // tail consume steps (chunk 15 spans ksteps 60,61 only)
        cstep<14, 2>(CTX_ARGS);
        cstep<14, 3>(CTX_ARGS);
        cstep<15, 0>(CTX_ARGS);
        cstep<15, 1>(CTX_ARGS);

        // ---- epilogue: out = x + D (f32; x path exact) ----
#define EPI(D0, D1, D2, D3, SU, NT) do {                                       \
        long long rlo = base + (SU) * 16 + g;                                  \
        int c = (NT) * 8 + 2 * t;                                              \
        const float2 xlo = *reinterpret_cast<const float2*>(x + rlo * NF + c); \
        float2 olo; olo.x = xlo.x + (D0); olo.y = xlo.y + (D1);                \
        *reinterpret_cast<float2*>(out + rlo * NF + c) = olo;                  \
        const float2 xhi = *reinterpret_cast<const float2*>(x + (rlo + 8) * NF + c); \
        float2 ohi; ohi.x = xhi.x + (D2); ohi.y = xhi.y + (D3);                \
        *reinterpret_cast<float2*>(out + (rlo + 8) * NF + c) = ohi;            \
    } while (0)
        EPI(d00, d01, d02, d03, 0, 0);
        EPI(d10, d11, d12, d13, 0, 1);
        EPI(d20, d21, d22, d23, 1, 0);
        EPI(d30, d31, d32, d33, 1, 1);
#undef EPI
    }
}

extern "C" void kernel_launch(void* const* d_in, const int* in_sizes, int n_in,
                              void* d_out, int out_size)
{
    const float* x = (const float*)d_in[0];   // [262144, 16]
    const float* W = (const float*)d_in[1];   // [969, 16]
    float* out = (float*)d_out;

    cudaFuncSetAttribute(taylor_mma,
                         cudaFuncAttributeMaxDynamicSharedMemorySize,
                         SMEM_TOTAL);

    reset_ticket_kernel<<<1, 1>>>();
    taylor_mma<<<GRID, BLOCK, SMEM_TOTAL>>>(x, W, out);
}

// round 14
// speedup vs baseline: 18.6645x; 1.0940x over previous
#include <cuda_runtime.h>
#include <cstdint>

// TaylorMap via classic mma.sync m16n8k16 f16/f32 (sm_103: no tcgen05).
//   out = x + P(x) @ W,  P:[B,969->992] monomials (reference order) in f16.
// R14 = R13 (58.1us, rel_err 1.1e-4) with the A staging rebuilt around wide
// ops: producer stores 8 k per STS.128 into a row-major XOR-swizzled stage;
// consumer fetches whole mma A-fragments with ldmatrix.m8n8.x4. Bytes through
// smem unchanged (the 36us crossbar floor) but smem instructions drop ~8x,
// releasing issue slots so L1 can run at its floor.

typedef unsigned int u32;
typedef unsigned long long u64;

#define NF 16
#define KTOT 992
#define NSTEP 62
#define BLOCK 256
#define GRID 296                    // 2 CTAs/SM
#define NBATCH 262144
#define NTILES (NBATCH / 32)        // 8192 tiles of 32 rows
#define BFRAG_BYTES (NSTEP * 32 * 16)     // 31744
#define PSM_OFF BFRAG_BYTES
#define PSM_PER_WARP 8192           // two 4KB chunk buffers (32 rows x 128B)
#define SMEM_TOTAL (BFRAG_BYTES + 8 * PSM_PER_WARP)   // 97280

#define ROW3(i, a, b) (153 + ((i) * ((i) + 1) * ((i) + 2)) / 6 \
                       + ((a) * ((a) + 1)) / 2 + (b))

__device__ unsigned int g_ticket;
__global__ void reset_ticket_kernel() { g_ticket = 0u; }

__device__ __forceinline__ u32 smem_u32(const void* p) {
    u32 a;
    asm("{ .reg .u64 t; cvta.to.shared.u64 t, %1; cvt.u32.u64 %0, t; }"
        : "=r"(a) : "l"(p));
    return a;
}
__device__ __forceinline__ u32 packf16(float hi, float lo) {
    u32 r; asm("cvt.rn.f16x2.f32 %0, %1, %2;" : "=r"(r) : "f"(hi), "f"(lo));
    return r;
}

// ---- tiny integer-sequence machinery (no std headers) ----
template <int... Is> struct ISeq {};
template <int N, int... Is> struct MkSeq : MkSeq<N - 1, N - 1, Is...> {};
template <int... Is> struct MkSeq<0, Is...> { using T = ISeq<Is...>; };

__host__ __device__ constexpr int pair_a(int p) {
    int a = 0;
    while ((a + 1) * (a + 2) / 2 <= p) a++;
    return a;
}

// ---- shared context parameter pack ----
#define CTX_DECL float (&xs)[16], float& pend,                                 \
    u32& s0, u32& s1, u32& s2, u32& s3,                                        \
    const u32 sa0, const u32 sa1, const u32 sa2, const u32 sa3,                \
    const u32 sa4, const u32 sa5, const u32 sa6, const u32 sa7,                \
    const u32 rsu0, const u32 rsu1,                                            \
    const u32 x0, const u32 x1, const u32 x2, const u32 x3, const u32 rb,      \
    float& d00, float& d01, float& d02, float& d03,                            \
    float& d10, float& d11, float& d12, float& d13,                            \
    float& d20, float& d21, float& d22, float& d23,                            \
    float& d30, float& d31, float& d32, float& d33
#define CTX_ARGS xs, pend, s0, s1, s2, s3, sa0, sa1, sa2, sa3, sa4, sa5, sa6,  \
    sa7, rsu0, rsu1, x0, x1, x2, x3, rb,                                       \
    d00, d01, d02, d03, d10, d11, d12, d13, d20, d21, d22, d23, d30, d31, d32, d33

// One consume k-step (chunk CH, step S): 1 B LDS.128 + 2 ldmatrix.x4 + 4 mma.
template <int CH, int S>
__device__ __forceinline__ void cstep(CTX_DECL) {
    constexpr u32 PAR = (u32)((CH & 1) * 4096);
    u32 xoff = (S == 0) ? x0 : (S == 1) ? x1 : (S == 2) ? x2 : x3;
    u32 b0, b1, b2, b3;
    asm volatile("ld.shared.v4.b32 {%0,%1,%2,%3}, [%4];"
        : "=r"(b0), "=r"(b1), "=r"(b2), "=r"(b3)
        : "r"(rb + (u32)((4 * CH + S) * 512)));
    u32 a0, a1, a2, a3;
    asm volatile("ldmatrix.sync.aligned.m8n8.x4.shared.b16 "
        "{%0,%1,%2,%3}, [%4];"
        : "=r"(a0), "=r"(a1), "=r"(a2), "=r"(a3)
        : "r"(rsu0 + PAR + xoff));
    asm volatile("mma.sync.aligned.m16n8k16.row.col.f32.f16.f16.f32 "
        "{%0,%1,%2,%3}, {%4,%5,%6,%7}, {%8,%9}, {%0,%1,%2,%3};"
        : "+f"(d00), "+f"(d01), "+f"(d02), "+f"(d03)
        : "r"(a0), "r"(a1), "r"(a2), "r"(a3), "r"(b0), "r"(b1));
    asm volatile("mma.sync.aligned.m16n8k16.row.col.f32.f16.f16.f32 "
        "{%0,%1,%2,%3}, {%4,%5,%6,%7}, {%8,%9}, {%0,%1,%2,%3};"
        : "+f"(d10), "+f"(d11), "+f"(d12), "+f"(d13)
        : "r"(a0), "r"(a1), "r"(a2), "r"(a3), "r"(b2), "r"(b3));
    u32 c0, c1, c2, c3;
    asm volatile("ldmatrix.sync.aligned.m8n8.x4.shared.b16 "
        "{%0,%1,%2,%3}, [%4];"
        : "=r"(c0), "=r"(c1), "=r"(c2), "=r"(c3)
        : "r"(rsu1 + PAR + xoff));
    asm volatile("mma.sync.aligned.m16n8k16.row.col.f32.f16.f16.f32 "
        "{%0,%1,%2,%3}, {%4,%5,%6,%7}, {%8,%9}, {%0,%1,%2,%3};"
        : "+f"(d20), "+f"(d21), "+f"(d22), "+f"(d23)
        : "r"(c0), "r"(c1), "r"(c2), "r"(c3), "r"(b0), "r"(b1));
    asm volatile("mma.sync.aligned.m16n8k16.row.col.f32.f16.f16.f32 "
        "{%0,%1,%2,%3}, {%4,%5,%6,%7}, {%8,%9}, {%0,%1,%2,%3};"
        : "+f"(d30), "+f"(d31), "+f"(d32), "+f"(d33)
        : "r"(c0), "r"(c1), "r"(c2), "r"(c3), "r"(b2), "r"(b3));
}

// Emit monomial KK (STRICTLY ASCENDING KK): pack f16 pairs into s0..s3,
// STS.128 every 8 k into the row-major swizzled stage, interleave one
// consume step per 16 k, syncwarp at each 64-k chunk end.
template <int KK>
__device__ __forceinline__ void emitk(float v, CTX_DECL) {
    if constexpr ((KK & 1) == 0) {
        pend = v;
    } else {
        u32 h = packf16(v, pend);
        constexpr int kp = KK >> 1;
        constexpr int sel = kp & 3;
        if constexpr (sel == 0) s0 = h;
        else if constexpr (sel == 1) s1 = h;
        else if constexpr (sel == 2) s2 = h;
        else {
            s3 = h;
            constexpr int j = kp >> 2;               // global 16B unit 0..123
            constexpr int j7 = j & 7;
            constexpr u32 PAR = (u32)(((j >> 3) & 1) * 4096);
            u32 base = (j7 == 0) ? sa0 : (j7 == 1) ? sa1 : (j7 == 2) ? sa2
                     : (j7 == 3) ? sa3 : (j7 == 4) ? sa4 : (j7 == 5) ? sa5
                     : (j7 == 6) ? sa6 : sa7;
            asm volatile("st.shared.v4.b32 [%0], {%1,%2,%3,%4};"
                :: "r"(base + PAR), "r"(s0), "r"(s1), "r"(s2), "r"(s3));
        }
        if constexpr (KK >= 79 && (KK & 15) == 15) {
            cstep<(KK >> 6) - 1, (KK >> 4) & 3>(CTX_ARGS);
        }
        if constexpr ((KK & 63) == 63) { __syncwarp(); }
    }
}

// ---- ascending-k traversal (validated in R13) ----
template <int... Is>
__device__ __forceinline__ void do_deg1(ISeq<Is...>, CTX_DECL) {
    (emitk<1 + Is>(xs[Is], CTX_ARGS), ...);
}
template <int P>
__device__ __forceinline__ void do_p2(CTX_DECL) {
    constexpr int A = pair_a(P);
    constexpr int B = P - A * (A + 1) / 2;
    emitk<17 + P>(xs[A] * xs[B], CTX_ARGS);
}
template <int... Ps>
__device__ __forceinline__ void do_deg2(ISeq<Ps...>, CTX_DECL) {
    (do_p2<Ps>(CTX_ARGS), ...);
}
template <int II, int A, int... Bs>
__device__ __forceinline__ void emit3run(float tp, ISeq<Bs...>, CTX_DECL) {
    (emitk<ROW3(II, A, Bs)>(tp * xs[Bs], CTX_ARGS), ...);
}
template <int II, int... As>
__device__ __forceinline__ void do_ii(ISeq<As...>, CTX_DECL) {
    (emit3run<II, As>(xs[II] * xs[As], typename MkSeq<As + 1>::T{}, CTX_ARGS), ...);
}
template <int... IIs>
__device__ __forceinline__ void do_deg3(ISeq<IIs...>, CTX_DECL) {
    (do_ii<IIs>(typename MkSeq<IIs + 1>::T{}, CTX_ARGS), ...);
}
template <int... Js>
__device__ __forceinline__ void do_pad(ISeq<Js...>, CTX_DECL) {
    (emitk<969 + Js>(0.0f, CTX_ARGS), ...);
}

__global__ void __launch_bounds__(BLOCK, 2)
taylor_mma(const float* __restrict__ x, const float* __restrict__ W,
           float* __restrict__ out)
{
    extern __shared__ unsigned char smem[];
    const u32 sbase = smem_u32(smem);
    const int tid = threadIdx.x;
    const int warp = tid >> 5;
    const int lane = tid & 31;
    const int g = lane >> 2;          // fragment row group 0..7
    const int t = lane & 3;           // thread-in-group 0..3

    // ---- build B fragments once (validated R7/R8/R13) ----
#pragma unroll 1
    for (int e = tid; e < NSTEP * 32; e += BLOCK) {
        int s = e >> 5, l = e & 31;
        int lg = l >> 2, lt = l & 3;
        int k1 = 16 * s + 2 * lt;
#define WGET(K, C) (((K) < 969) ? W[(K) * NF + (C)] : 0.0f)
        uint4 v;
        v.x = packf16(WGET(k1 + 1, lg),     WGET(k1, lg));
        v.y = packf16(WGET(k1 + 9, lg),     WGET(k1 + 8, lg));
        v.z = packf16(WGET(k1 + 1, lg + 8), WGET(k1, lg + 8));
        v.w = packf16(WGET(k1 + 9, lg + 8), WGET(k1 + 8, lg + 8));
#undef WGET
        *reinterpret_cast<uint4*>(smem + e * 16) = v;
    }
    __syncthreads();

    // ---- stage addressing (row-major, unit swizzle phys=(u^(row&7))*16) ----
    const u32 stg = sbase + PSM_OFF + warp * PSM_PER_WARP;   // buf0; buf1=+4096
    const u32 l7 = (u32)(lane & 7);
    const u32 rowb = stg + (u32)lane * 128;
    // producer store bases for logical units 0..7 (this lane's row)
    const u32 sa0 = rowb + ((0u ^ l7) << 4);
    const u32 sa1 = rowb + ((1u ^ l7) << 4);
    const u32 sa2 = rowb + ((2u ^ l7) << 4);
    const u32 sa3 = rowb + ((3u ^ l7) << 4);
    const u32 sa4 = rowb + ((4u ^ l7) << 4);
    const u32 sa5 = rowb + ((5u ^ l7) << 4);
    const u32 sa6 = rowb + ((6u ^ l7) << 4);
    const u32 sa7 = rowb + ((7u ^ l7) << 4);
    // consumer ldmatrix row bases: R = lane&15 (su0 rows 0..15; su1 +16)
    const u32 rsu0 = stg + (u32)(lane & 15) * 128;
    const u32 rsu1 = rsu0 + 2048;
    // per-step unit offsets: x_S = ((2S + lane>>4) ^ (lane&7)) << 4
    const u32 lu = (u32)(lane >> 4);
    const u32 x0 = ((0u + lu) ^ l7) << 4;
    const u32 x1 = ((2u + lu) ^ l7) << 4;
    const u32 x2 = ((4u + lu) ^ l7) << 4;
    const u32 x3 = ((6u + lu) ^ l7) << 4;
    const u32 rb = sbase + lane * 16;    // B fragment base

    for (;;) {
        u32 tk;
        if (lane == 0) tk = atomicAdd(&g_ticket, 1u);
        tk = __shfl_sync(0xffffffffu, tk, 0);
        if (tk >= NTILES) break;

        const long long base = (long long)tk * 32;

        const float4* xv = reinterpret_cast<const float4*>(x + (base + lane) * NF);
        float4 v0 = xv[0], v1 = xv[1], v2 = xv[2], v3 = xv[3];
        float xs[NF] = { v0.x, v0.y, v0.z, v0.w,  v1.x, v1.y, v1.z, v1.w,
                         v2.x, v2.y, v2.z, v2.w,  v3.x, v3.y, v3.z, v3.w };

        float d00 = 0, d01 = 0, d02 = 0, d03 = 0;   // su0,nt0
        float d10 = 0, d11 = 0, d12 = 0, d13 = 0;   // su0,nt1
        float d20 = 0, d21 = 0, d22 = 0, d23 = 0;   // su1,nt0
        float d30 = 0, d31 = 0, d32 = 0, d33 = 0;   // su1,nt1
        float pend = 0.0f;
        u32 s0 = 0, s1 = 0, s2 = 0, s3 = 0;

        // ---- fully-expanded generation, ascending k = 0..991 ----
        emitk<0>(1.0f, CTX_ARGS);
        do_deg1(typename MkSeq<16>::T{}, CTX_ARGS);
        do_deg2(typename MkSeq<136>::T{}, CTX_ARGS);
        do_deg3(typename MkSeq<16>::T{}, CTX_ARGS);
        do_pad(typename MkSeq<KTOT - 969>::T{}, CTX_ARGS);

        // tail consume steps (chunk 15 spans ksteps 60,61 only)
        cstep<14, 2>(CTX_ARGS);
        cstep<14, 3>(CTX_ARGS);
        cstep<15, 0>(CTX_ARGS);
        cstep<15, 1>(CTX_ARGS);

        // ---- epilogue: out = x + D (f32; x path exact) ----
#define EPI(D0, D1, D2, D3, SU, NT) do {                                       \
        long long rlo = base + (SU) * 16 + g;                                  \
        int c = (NT) * 8 + 2 * t;                                              \
        const float2 xlo = *reinterpret_cast<const float2*>(x + rlo * NF + c); \
        float2 olo; olo.x = xlo.x + (D0); olo.y = xlo.y + (D1);                \
        *reinterpret_cast<float2*>(out + rlo * NF + c) = olo;                  \
        const float2 xhi = *reinterpret_cast<const float2*>(x + (rlo + 8) * NF + c); \
        float2 ohi; ohi.x = xhi.x + (D2); ohi.y = xhi.y + (D3);                \
        *reinterpret_cast<float2*>(out + (rlo + 8) * NF + c) = ohi;            \
    } while (0)
        EPI(d00, d01, d02, d03, 0, 0);
        EPI(d10, d11, d12, d13, 0, 1);
        EPI(d20, d21, d22, d23, 1, 0);
        EPI(d30, d31, d32, d33, 1, 1);
#undef EPI
    }
}

extern "C" void kernel_launch(void* const* d_in, const int* in_sizes, int n_in,
                              void* d_out, int out_size)
{
    const float* x = (const float*)d_in[0];   // [262144, 16]
    const float* W = (const float*)d_in[1];   // [969, 16]
    float* out = (float*)d_out;

    cudaFuncSetAttribute(taylor_mma,
                         cudaFuncAttributeMaxDynamicSharedMemorySize,
                         SMEM_TOTAL);

    reset_ticket_kernel<<<1, 1>>>();
    taylor_mma<<<GRID, BLOCK, SMEM_TOTAL>>>(x, W, out);
}